// round 14
// baseline (speedup 1.0000x reference)
#include <cuda_runtime.h>

#define FULL 0xFFFFFFFFu

// Problem constants
#define BATCH 32
#define IN    2048
#define OUT   2048
#define KNUM  8
#define HDIM  512
#define KSZ   (IN * OUT)          // 4M elements per expert
#define XSTR  516                 // x_s row stride

// Scratch (device globals; fully overwritten/reset every call -> replay safe)
__device__ float    g_h[HDIM];
__device__ unsigned g_ticket;
__device__ float    g_alpha[KNUM];
__device__ float    g_wagg[KSZ];      // 16 MB aggregated weights

// ---------------------------------------------------------------------------
// K1: fused MLP (proven): partial cond@w1 -> atomic g_h; zero out-slice;
// last block finishes relu/w2/softmax -> g_alpha; resets scratch.
// ---------------------------------------------------------------------------
__global__ void mlp_kernel(const float* __restrict__ cond,
                           const float* __restrict__ w1,
                           const float* __restrict__ b1,
                           const float* __restrict__ w2,
                           const float* __restrict__ b2,
                           float* __restrict__ out) {
    __shared__ float    h_s[HDIM];
    __shared__ float    s_s[KNUM];
    __shared__ unsigned rank_s;

    int j  = threadIdx.x;         // 0..511
    int p  = blockIdx.x;          // 0..127
    int i0 = p * 16;

    float s[8];
#pragma unroll
    for (int u = 0; u < 8; ++u)
        s[u] = cond[i0 + u] * w1[(i0 + u) * HDIM + j];
#pragma unroll
    for (int u = 0; u < 8; ++u)
        s[u] += cond[i0 + 8 + u] * w1[(i0 + 8 + u) * HDIM + j];
    float sum = ((s[0] + s[1]) + (s[2] + s[3])) + ((s[4] + s[5]) + (s[6] + s[7]));

    atomicAdd(&g_h[j], sum);
    out[p * HDIM + j] = 0.f;      // zero out for gemv's atomic accumulation

    __threadfence();
    __syncthreads();
    if (j == 0) rank_s = atomicAdd(&g_ticket, 1u);
    __syncthreads();
    if (rank_s != gridDim.x - 1) return;

    __threadfence();
    h_s[j] = fmaxf(g_h[j] + b1[j], 0.f);
    __syncthreads();

    int wid = j >> 5, lane = j & 31;
    if (wid < KNUM) {
        float sc = 0.f;
#pragma unroll
        for (int m = 0; m < HDIM / 32; ++m) {
            int jj = lane + m * 32;
            sc += h_s[jj] * w2[jj * KNUM + wid];
        }
#pragma unroll
        for (int off = 16; off; off >>= 1) sc += __shfl_xor_sync(FULL, sc, off);
        if (lane == 0) s_s[wid] = sc + b2[wid];
    }
    __syncthreads();
    if (j == 0) {
        float mx = -1e30f;
#pragma unroll
        for (int k = 0; k < KNUM; ++k) mx = fmaxf(mx, s_s[k]);
        float e[KNUM];
        float ssum = 0.f;
#pragma unroll
        for (int k = 0; k < KNUM; ++k) { e[k] = __expf(s_s[k] - mx); ssum += e[k]; }
        float inv = 1.f / ssum;
#pragma unroll
        for (int k = 0; k < KNUM; ++k) g_alpha[k] = e[k] * inv;
        g_ticket = 0;
    }
    g_h[j] = 0.f;
}

// ---------------------------------------------------------------------------
// K2: expert aggregation as a PURE STREAM.
// w_agg[e] = sum_k a_k * kw[k][e]. Grid-stride float4; chip-wide the reads
// form 8 contiguous moving fronts (one per expert plane) -> HBM row-hit
// friendly, unlike the fused kernels' 20-40K scattered fine-grained streams.
// ---------------------------------------------------------------------------
__global__ __launch_bounds__(256) void agg_kernel(const float* __restrict__ kw) {
    const float4* kw4 = reinterpret_cast<const float4*>(kw);
    float4*       wg4 = reinterpret_cast<float4*>(g_wagg);

    float a[KNUM];
#pragma unroll
    for (int k = 0; k < KNUM; ++k) a[k] = g_alpha[k];

    int stride = gridDim.x * blockDim.x;
    for (int e = blockIdx.x * blockDim.x + threadIdx.x; e < KSZ / 4; e += stride) {
        float4 v0 = kw4[0u * (KSZ / 4) + e];
        float4 v1 = kw4[1u * (KSZ / 4) + e];
        float4 v2 = kw4[2u * (KSZ / 4) + e];
        float4 v3 = kw4[3u * (KSZ / 4) + e];
        float4 v4 = kw4[4u * (KSZ / 4) + e];
        float4 v5 = kw4[5u * (KSZ / 4) + e];
        float4 v6 = kw4[6u * (KSZ / 4) + e];
        float4 v7 = kw4[7u * (KSZ / 4) + e];
        float4 r;
        r.x = ((a[0]*v0.x + a[1]*v1.x) + (a[2]*v2.x + a[3]*v3.x)) +
              ((a[4]*v4.x + a[5]*v5.x) + (a[6]*v6.x + a[7]*v7.x));
        r.y = ((a[0]*v0.y + a[1]*v1.y) + (a[2]*v2.y + a[3]*v3.y)) +
              ((a[4]*v4.y + a[5]*v5.y) + (a[6]*v6.y + a[7]*v7.y));
        r.z = ((a[0]*v0.z + a[1]*v1.z) + (a[2]*v2.z + a[3]*v3.z)) +
              ((a[4]*v4.z + a[5]*v5.z) + (a[6]*v6.z + a[7]*v7.z));
        r.w = ((a[0]*v0.w + a[1]*v1.w) + (a[2]*v2.w + a[3]*v3.w)) +
              ((a[4]*v4.w + a[5]*v5.w) + (a[6]*v6.w + a[7]*v7.w));
        wg4[e] = r;
    }
}

// ---------------------------------------------------------------------------
// K3: out[b,o] (+)= sum_{i in chunk} w_agg[o,i] * x[b,i]  (+ bias at c==0)
// grid = 1024 blocks (256 ob x 4 c) x 256 threads (8 warps x 1 o).
// Warp preloads its full 512-float w_agg strip into 8 float4 regs (og-dup,
// L2-mostly); lane = (io 4-i slice, og batch half), acc[16]; smem-transpose
// epilogue + atomicAdd (out zeroed in mlp_kernel).
// ---------------------------------------------------------------------------
__global__ __launch_bounds__(256) void gemv_kernel(
        const float* __restrict__ x,    // [32, 2048]
        const float* __restrict__ kb,   // [8, 2048]
        float* __restrict__ out) {      // [32, 2048]
    extern __shared__ float sm[];
    float* x_s    = sm;                           // 32 * 516 floats
    float* a_s    = sm + BATCH * XSTR;            // 8
    float* part_s = sm;                           // alias x_s after compute

    int t    = threadIdx.x;
    int wid  = t >> 5;
    int lane = t & 31;
    int io   = lane & 15;
    int og   = lane >> 4;
    int ob   = blockIdx.x & 255;                  // 0..255
    int c    = blockIdx.x >> 8;                   // 0..3
    int i0   = c * 512;
    int o    = ob * 8 + wid;
    int b0   = og * 16;

    if (t < KNUM) a_s[t] = g_alpha[t];

    // preload full w_agg strip: 8 quarters x 1 float4 (og halves duplicate)
    const float* wbase = g_wagg + (size_t)o * IN + i0 + io * 4;
    float4 wv[8];
#pragma unroll
    for (int q = 0; q < 8; ++q)
        wv[q] = *reinterpret_cast<const float4*>(wbase + q * 64);

    // stage x tile: x_s[b][il] = x[b][i0+il]
    const float4* x4 = reinterpret_cast<const float4*>(x);
#pragma unroll
    for (int jj = 0; jj < (BATCH * 512) / (4 * 256); ++jj) {
        int idx = jj * 256 + t;                   // 0..4095 float4 units
        int b   = idx >> 7;                       // 128 f4 per row
        int il4 = idx & 127;
        *reinterpret_cast<float4*>(&x_s[b * XSTR + il4 * 4]) =
            x4[(b * IN + i0) / 4 + il4];
    }
    __syncthreads();

    float acc[16];
#pragma unroll
    for (int bb = 0; bb < 16; ++bb) acc[bb] = 0.f;

#pragma unroll
    for (int q = 0; q < 8; ++q) {
        const float* xrow = x_s + b0 * XSTR + q * 64 + io * 4;
        float4 w4 = wv[q];
#pragma unroll
        for (int bb = 0; bb < 16; ++bb) {
            float4 xq = *reinterpret_cast<const float4*>(xrow + bb * XSTR);
            acc[bb] += w4.x * xq.x;
            acc[bb] += w4.y * xq.y;
            acc[bb] += w4.z * xq.z;
            acc[bb] += w4.w * xq.w;
        }
    }

    // epilogue: partials into smem (alias x_s), reduce over io
    __syncthreads();                  // all warps done reading x_s
#pragma unroll
    for (int bb = 0; bb < 16; ++bb)
        part_s[((b0 + bb) * 8 + wid) * 17 + io] = acc[bb];
    __syncthreads();

    {
        int b   = t >> 3;             // 0..31
        int oi2 = t & 7;              // 0..7
        const float* p = &part_s[t * 17];
        float s0 = 0.f, s1 = 0.f;
#pragma unroll
        for (int j = 0; j < 16; j += 2) { s0 += p[j]; s1 += p[j + 1]; }
        float v = s0 + s1;
        if (c == 0) {
            int o2 = ob * 8 + oi2;
            float bb2 = 0.f;
#pragma unroll
            for (int k = 0; k < KNUM; ++k) bb2 += a_s[k] * kb[k * OUT + o2];
            v += bb2;
        }
        atomicAdd(&out[b * OUT + ob * 8 + oi2], v);
    }
}

// ---------------------------------------------------------------------------
extern "C" void kernel_launch(void* const* d_in, const int* in_sizes, int n_in,
                              void* d_out, int out_size) {
    const float* x    = (const float*)d_in[0];
    const float* cond = (const float*)d_in[1];
    const float* w1   = (const float*)d_in[2];
    const float* b1   = (const float*)d_in[3];
    const float* w2   = (const float*)d_in[4];
    const float* b2   = (const float*)d_in[5];
    const float* kw   = (const float*)d_in[6];
    const float* kb   = (const float*)d_in[7];
    float* out = (float*)d_out;

    const int SMEM_GEMV = (BATCH * XSTR + 8) * 4;   // ~66 KB
    static int smem_set = 0;
    if (!smem_set) {
        cudaFuncSetAttribute(gemv_kernel,
                             cudaFuncAttributeMaxDynamicSharedMemorySize,
                             SMEM_GEMV);
        smem_set = 1;
    }

    mlp_kernel<<<128, HDIM>>>(cond, w1, b1, w2, b2, out);
    agg_kernel<<<1184, 256>>>(kw);                  // 8 blocks/SM target
    gemv_kernel<<<1024, 256, SMEM_GEMV>>>(x, kb, out);
}

// round 15
// speedup vs baseline: 1.3672x; 1.3672x over previous
#include <cuda_runtime.h>

#define FULL 0xFFFFFFFFu

// Problem constants
#define BATCH 32
#define IN    2048
#define OUT   2048
#define KNUM  8
#define HDIM  512
#define KSZ   (IN * OUT)          // 4M elements per expert

#define IBLK   512                // i-range per block (8 quarters of 64)
#define NCHUNK (IN / IBLK)        // 4
#define NQ     (IBLK / 64)        // 8
#define OBLK   16                 // o's per block (8 warps x 2 o)
#define NOBLK  (OUT / OBLK)       // 128
#define GRID   (NCHUNK * NOBLK)   // 512
#define XSTR   516                // x_s row stride

// Scratch (device globals; reset in-kernel every call -> graph-replay safe)
__device__ float             g_h[HDIM];     // zero-init; reset by finisher
__device__ unsigned          g_ticket;      // reset by finisher
__device__ unsigned          g_done;        // reset by completion ticket
__device__ volatile unsigned g_flag;        // reset by completion ticket
__device__ float             g_alpha[KNUM];

// ---------------------------------------------------------------------------
// ONE kernel. Blocks 0..127 (c==0) run the MLP phase first (partial cond@w1,
// atomic -> g_h, zero out-slice; ticket-elected finisher does relu/w2/softmax
// -> g_alpha, sets g_flag). ALL blocks issue quarter-0 kw loads + x staging
// BEFORE spinning on g_flag, so the MLP hides under main's own DRAM fill.
// Main body = R11's proven 34.5us structure (thread owns o = wid*2+og,
// io 4-i slice, full-batch acc[32], distance-1 quarter prefetch, registers-
// only aggregated weights, smem-transpose epilogue + atomicAdd).
// ---------------------------------------------------------------------------
__global__ __launch_bounds__(256, 2) void fused_kernel(
        const float* __restrict__ x,     // [32, 2048]
        const float* __restrict__ cond,  // [1, 2048]
        const float* __restrict__ w1,    // [2048, 512]
        const float* __restrict__ b1,    // [512]
        const float* __restrict__ w2,    // [512, 8]
        const float* __restrict__ b2,    // [8]
        const float* __restrict__ kw,    // [8, 2048, 2048]
        const float* __restrict__ kb,    // [8, 2048]
        float* __restrict__ out) {       // [32, 2048]
    extern __shared__ float sm[];
    float* x_s    = sm;                  // 32 * 516 floats (~66 KB)
    float* h_s    = sm;                  // alias during MLP phase (512 floats)
    float* part_s = sm;                  // alias after compute
    __shared__ float    s_s[KNUM];
    __shared__ unsigned rank_s;

    int t    = threadIdx.x;
    int wid  = t >> 5;
    int lane = t & 31;
    int io   = lane & 15;
    int og   = lane >> 4;
    int ob   = blockIdx.x & (NOBLK - 1);          // 0..127
    int c    = blockIdx.x >> 7;                   // 0..3
    int i0   = c * IBLK;
    int oi   = wid * 2 + og;                      // 0..15
    int o    = ob * OBLK + oi;

    // ================= Phase A: MLP (blocks 0..127 only) =================
    if (blockIdx.x < 128) {
        int i0m = blockIdx.x * 16;
        float sA = 0.f, sB = 0.f;
#pragma unroll
        for (int i = 0; i < 16; ++i) {
            float cv = cond[i0m + i];
            sA += cv * w1[(i0m + i) * HDIM + t];
            sB += cv * w1[(i0m + i) * HDIM + t + 256];
        }
        atomicAdd(&g_h[t], sA);
        atomicAdd(&g_h[t + 256], sB);
        out[blockIdx.x * 512 + t]       = 0.f;    // zero out for epilogue adds
        out[blockIdx.x * 512 + t + 256] = 0.f;

        __threadfence();
        __syncthreads();
        if (t == 0) rank_s = atomicAdd(&g_ticket, 1u);
        __syncthreads();

        if (rank_s == 127) {              // finisher block
            __threadfence();
            h_s[t]       = fmaxf(g_h[t] + b1[t], 0.f);
            h_s[t + 256] = fmaxf(g_h[t + 256] + b1[t + 256], 0.f);
            g_h[t] = 0.f; g_h[t + 256] = 0.f;     // reset for next replay
            if (t == 0) g_ticket = 0;
            __syncthreads();

            if (wid < KNUM) {             // 8 warps, one score each
                float sc = 0.f;
#pragma unroll
                for (int m = 0; m < HDIM / 32; ++m) {
                    int jj = lane + m * 32;
                    sc += h_s[jj] * w2[jj * KNUM + wid];
                }
#pragma unroll
                for (int off = 16; off; off >>= 1)
                    sc += __shfl_xor_sync(FULL, sc, off);
                if (lane == 0) s_s[wid] = sc + b2[wid];
            }
            __syncthreads();              // h_s reads done before x staging
            if (t == 0) {
                float mx = -1e30f;
#pragma unroll
                for (int k = 0; k < KNUM; ++k) mx = fmaxf(mx, s_s[k]);
                float e[KNUM];
                float ssum = 0.f;
#pragma unroll
                for (int k = 0; k < KNUM; ++k) {
                    e[k] = __expf(s_s[k] - mx); ssum += e[k];
                }
                float inv = 1.f / ssum;
#pragma unroll
                for (int k = 0; k < KNUM; ++k) g_alpha[k] = e[k] * inv;
                __threadfence();
                g_flag = 1;               // release
            }
        }
    }

    // ======= Phase B: issue alpha-independent DRAM work, THEN spin =======
    const float* base = kw + (size_t)o * IN + i0 + io * 4;
    float4 cur[KNUM];
#pragma unroll
    for (int k = 0; k < KNUM; ++k)
        cur[k] = *reinterpret_cast<const float4*>(base + (size_t)k * KSZ);

    // stage x tile: x_s[b][il] = x[b][i0+il]
    const float4* x4 = reinterpret_cast<const float4*>(x);
#pragma unroll
    for (int jj = 0; jj < (BATCH * IBLK) / (4 * 256); ++jj) {
        int idx = jj * 256 + t;                   // 0..4095 float4 units
        int b   = idx >> 7;                       // 128 f4 per row
        int il4 = idx & 127;
        *reinterpret_cast<float4*>(&x_s[b * XSTR + il4 * 4]) =
            x4[(b * IN + i0) / 4 + il4];
    }

    // spin: one thread polls, block parks at the barrier
    if (t == 0) {
        while (g_flag == 0) __nanosleep(128);
    }
    __syncthreads();
    __threadfence();                      // acquire side

    float a[KNUM];
#pragma unroll
    for (int k = 0; k < KNUM; ++k) a[k] = __ldcg(&g_alpha[k]);

    // ===================== Phase C: main loop (R11) =======================
    float acc[BATCH];
#pragma unroll
    for (int b = 0; b < BATCH; ++b) acc[b] = 0.f;

    for (int q = 0; q < NQ; ++q) {
        // aggregate experts into registers (consumes cur)
        float4 w4;
        w4.x = a[0] * cur[0].x; w4.y = a[0] * cur[0].y;
        w4.z = a[0] * cur[0].z; w4.w = a[0] * cur[0].w;
#pragma unroll
        for (int k = 1; k < KNUM; ++k) {
            float ak = a[k];
            w4.x += ak * cur[k].x; w4.y += ak * cur[k].y;
            w4.z += ak * cur[k].z; w4.w += ak * cur[k].w;
        }

        // prefetch next quarter (lands during this quarter's compute)
        if (q < NQ - 1) {
            const float* nb = base + (q + 1) * 64;
#pragma unroll
            for (int k = 0; k < KNUM; ++k)
                cur[k] = *reinterpret_cast<const float4*>(nb + (size_t)k * KSZ);
        }

        // compute: full batch, 1 LDS.128 + 4 FMA per b (og-broadcast x)
        const float* xrow = x_s + q * 64 + io * 4;
#pragma unroll
        for (int b = 0; b < BATCH; ++b) {
            float4 xq = *reinterpret_cast<const float4*>(xrow + b * XSTR);
            acc[b] += w4.x * xq.x;
            acc[b] += w4.y * xq.y;
            acc[b] += w4.z * xq.z;
            acc[b] += w4.w * xq.w;
        }
    }

    // ============ epilogue: smem transpose-reduce + atomicAdd ============
    __syncthreads();                      // all warps done reading x_s
#pragma unroll
    for (int b = 0; b < BATCH; ++b)
        part_s[(b * 16 + oi) * 17 + io] = acc[b];
    __syncthreads();

#pragma unroll
    for (int r = 0; r < 2; ++r) {
        int e   = r * 256 + t;            // 0..511 = b*16 + oi2
        int b   = e >> 4;
        int oi2 = e & 15;
        const float* p = &part_s[e * 17];
        float s0 = 0.f, s1 = 0.f;
#pragma unroll
        for (int j = 0; j < 16; j += 2) { s0 += p[j]; s1 += p[j + 1]; }
        float v = s0 + s1;
        if (c == 0) {                     // fold aggregated bias once
            int o2 = ob * OBLK + oi2;
            float bb = 0.f;
#pragma unroll
            for (int k = 0; k < KNUM; ++k) bb += a[k] * kb[k * OUT + o2];
            v += bb;
        }
        atomicAdd(&out[b * OUT + ob * OBLK + oi2], v);
    }

    // ============ completion ticket: reset flag for next replay ==========
    __threadfence();
    __syncthreads();
    if (t == 0) {
        unsigned r = atomicAdd(&g_done, 1u);
        if (r == GRID - 1) {              // everyone is past the spin
            g_done = 0;
            g_flag = 0;
        }
    }
}

// ---------------------------------------------------------------------------
extern "C" void kernel_launch(void* const* d_in, const int* in_sizes, int n_in,
                              void* d_out, int out_size) {
    const float* x    = (const float*)d_in[0];
    const float* cond = (const float*)d_in[1];
    const float* w1   = (const float*)d_in[2];
    const float* b1   = (const float*)d_in[3];
    const float* w2   = (const float*)d_in[4];
    const float* b2   = (const float*)d_in[5];
    const float* kw   = (const float*)d_in[6];
    const float* kb   = (const float*)d_in[7];
    float* out = (float*)d_out;

    const int SMEM = (BATCH * XSTR) * 4;          // 66048 B
    static int smem_set = 0;
    if (!smem_set) {
        cudaFuncSetAttribute(fused_kernel,
                             cudaFuncAttributeMaxDynamicSharedMemorySize,
                             SMEM);
        smem_set = 1;
    }

    fused_kernel<<<GRID, 256, SMEM>>>(x, cond, w1, b1, w2, b2, kw, kb, out);
}